// round 4
// baseline (speedup 1.0000x reference)
#include <cuda_runtime.h>
#include <math.h>

// ---------------------------------------------------------------------------
// BFM factorization-machine scoring, sparsity-aware, single fused kernel,
// inline scatter-accumulate (no compaction list, no finisher gather chain).
//   y = w0 + x.w_bias + u.t + t.b + 0.5*(b.b - sum_b_sq) + u.b
//   out = sigmoid(y * delta)
// Threads that discover a nonzero x[i] immediately gather wb[i] and the
// 64-float embedding row and atomically accumulate into global vectors.
// The last block to finish reduces 3x64 floats + 2 scalars and writes out.
// ---------------------------------------------------------------------------

#define KDIM 64
#define TPB  512
#define SEGS 4   // float4s per thread

__device__ float g_u[KDIM];
__device__ float g_t[KDIM];
__device__ float g_b[KDIM];
__device__ float g_bias = 0.f;
__device__ float g_absq = 0.f;
__device__ int   g_done = 0;

__device__ __forceinline__ void process_nz(int idx, float v,
                                           const float* __restrict__ wb,
                                           const float* __restrict__ uV,
                                           const float* __restrict__ tV,
                                           const float* __restrict__ bV,
                                           int N, int M)
{
    atomicAdd(&g_bias, v * __ldg(wb + idx));

    const float* row;
    float* acc;
    bool isB = false;
    if (idx < N)            { row = uV + (size_t)idx * KDIM;           acc = g_u; }
    else if (idx < N + M)   { row = tV + (size_t)(idx - N) * KDIM;     acc = g_t; }
    else                    { row = bV + (size_t)(idx - N - M) * KDIM; acc = g_b; isB = true; }

    float absq = 0.f;
    #pragma unroll
    for (int c = 0; c < KDIM / 4; ++c) {
        float4 e = reinterpret_cast<const float4*>(row)[c];
        atomicAdd(acc + 4 * c + 0, v * e.x);
        atomicAdd(acc + 4 * c + 1, v * e.y);
        atomicAdd(acc + 4 * c + 2, v * e.z);
        atomicAdd(acc + 4 * c + 3, v * e.w);
        if (isB) absq += e.x * e.x + e.y * e.y + e.z * e.z + e.w * e.w;
    }
    if (isB) atomicAdd(&g_absq, v * absq);
}

__global__ void __launch_bounds__(TPB, 2)
bfm_kernel(const float* __restrict__ x,
           const float* __restrict__ wb,
           const float* __restrict__ w0,
           const float* __restrict__ delta,
           const float* __restrict__ uV,
           const float* __restrict__ tV,
           const float* __restrict__ bV,
           float* __restrict__ out,
           int out_size, int P4, int P, int N, int M, int nblocks)
{
    const int tid = threadIdx.x;
    const int base4 = blockIdx.x * (TPB * SEGS);

    // ---- scan: 4 coalesced float4 loads per thread, all in flight ----
    float4 xv[SEGS];
    int    ok[SEGS];
    #pragma unroll
    for (int s = 0; s < SEGS; ++s) {
        int i4 = base4 + s * TPB + tid;
        ok[s] = (i4 < P4);
        if (ok[s]) xv[s] = reinterpret_cast<const float4*>(x)[i4];
    }
    #pragma unroll
    for (int s = 0; s < SEGS; ++s) {
        if (!ok[s]) continue;
        int base = (base4 + s * TPB + tid) * 4;
        if (xv[s].x != 0.f) process_nz(base + 0, xv[s].x, wb, uV, tV, bV, N, M);
        if (xv[s].y != 0.f) process_nz(base + 1, xv[s].y, wb, uV, tV, bV, N, M);
        if (xv[s].z != 0.f) process_nz(base + 2, xv[s].z, wb, uV, tV, bV, N, M);
        if (xv[s].w != 0.f) process_nz(base + 3, xv[s].w, wb, uV, tV, bV, N, M);
    }
    // tail (P not multiple of 4)
    if (blockIdx.x == 0 && tid == 0) {
        for (int r = P4 * 4; r < P; ++r) {
            float v = x[r];
            if (v != 0.f) process_nz(r, v, wb, uV, tV, bV, N, M);
        }
    }

    // ---- last-block election (release: barrier + thread-0 fence) ----
    __syncthreads();
    __shared__ int s_last;
    if (tid == 0) {
        __threadfence();                       // release this block's atomics
        int d = atomicAdd(&g_done, 1);
        s_last = (d == nblocks - 1);
        if (s_last) __threadfence();           // acquire all blocks' atomics
    }
    __syncthreads();
    if (!s_last) return;

    // ---- finisher: one round-trip read + tiny reduction ----
    __shared__ float s_part[2];
    __shared__ float s_bias, s_absq;
    if (tid == 0) { s_bias = __ldcg(&g_bias); s_absq = __ldcg(&g_absq); }
    if (tid < KDIM) {
        float u = __ldcg(&g_u[tid]);
        float t = __ldcg(&g_t[tid]);
        float b = __ldcg(&g_b[tid]);
        float lane = u * t + t * b + u * b + 0.5f * b * b;
        #pragma unroll
        for (int off = 16; off > 0; off >>= 1)
            lane += __shfl_down_sync(0xffffffffu, lane, off);
        if ((tid & 31) == 0) s_part[tid >> 5] = lane;
        // reset accumulators for next replay
        g_u[tid] = 0.f; g_t[tid] = 0.f; g_b[tid] = 0.f;
    }
    __syncthreads();
    if (tid == 0) {
        float y = w0[0] + s_bias + s_part[0] + s_part[1] - 0.5f * s_absq;
        float z = y * delta[0];
        float r = 1.f / (1.f + expf(-z));
        for (int q = 0; q < out_size; ++q) out[q] = r;
        g_bias = 0.f; g_absq = 0.f; g_done = 0;   // reset for next replay
    }
}

extern "C" void kernel_launch(void* const* d_in, const int* in_sizes, int n_in,
                              void* d_out, int out_size)
{
    const float* x     = (const float*)d_in[0];
    const float* delta = (const float*)d_in[1];
    /* pmi = d_in[2] unused */
    const float* w0    = (const float*)d_in[3];
    const float* wb    = (const float*)d_in[4];
    const float* uV    = (const float*)d_in[5];
    const float* tV    = (const float*)d_in[6];
    const float* bV    = (const float*)d_in[7];

    int P  = in_sizes[0];
    int N  = in_sizes[5] / KDIM;
    int M  = in_sizes[6] / KDIM;
    int P4 = P / 4;
    int per_block = TPB * SEGS;
    int blocks = (P4 + per_block - 1) / per_block;

    bfm_kernel<<<blocks, TPB>>>(x, wb, w0, delta, uV, tV, bV,
                                (float*)d_out, out_size, P4, P, N, M, blocks);
}